// round 16
// baseline (speedup 1.0000x reference)
#include <cuda_runtime.h>
#include <cuda_fp16.h>
#include <cstdint>

#define B_  32
#define CI_ 64
#define CO_ 64
#define Hh  128
#define Ww  128
#define NE  5
#define NT  10
#define NTILES 1024
#define NCTA   148

// ---- conv smem layout (bytes) ----
#define A0_OFF     0          // 8 slots * 132 px * 32B = 33792
#define A1_OFF     33792
#define B0_OFF     67584      // 25 taps * 64 o * 32B = 51200
#define B1_OFF     118784
#define SMEM_TOTAL 169984

// aux kernel block partitioning: synth first, then prepack (2px/thread), tail
#define SY_BLKS        (B_ * (CO_ / 4))           // 512
#define PP_PAIRS       (132 * 66)                 // 8712 pairs per (b,c)
#define PP_BLKS_PER_C  35                         // ceil(8712/256)
#define PP_BLKS        (PP_BLKS_PER_C * 4 * B_)   // 4480
#define AUX_BLKS       (SY_BLKS + PP_BLKS + 1)    // 4993

// B prepack: [b][chunk4][ky5][kx5][o64][ci16] fp16
__device__ uint4 g_wB4[409600];
// A prepack: [b][chunk4][yy132][xx132][ci16] fp16 (halo baked in as zeros)
__device__ uint4 g_xpack[4460544];

// ---------------------------------------------------------------------------
static __device__ __forceinline__ uint32_t smem_u32(const void* p) {
    uint32_t a;
    asm("{ .reg .u64 t; cvta.to.shared.u64 t, %1; cvt.u32.u64 %0, t; }"
        : "=r"(a) : "l"(p));
    return a;
}
static __device__ __forceinline__ void ldsm_x4(uint32_t* a, uint32_t addr) {
    asm volatile("ldmatrix.sync.aligned.m8n8.x4.shared.b16 {%0,%1,%2,%3}, [%4];"
                 : "=r"(a[0]), "=r"(a[1]), "=r"(a[2]), "=r"(a[3]) : "r"(addr));
}
static __device__ __forceinline__ void mma16816(float* d, const uint32_t* a,
                                                uint32_t b0, uint32_t b1) {
    asm volatile(
        "mma.sync.aligned.m16n8k16.row.col.f32.f16.f16.f32 "
        "{%0,%1,%2,%3}, {%4,%5,%6,%7}, {%8,%9}, {%0,%1,%2,%3};"
        : "+f"(d[0]), "+f"(d[1]), "+f"(d[2]), "+f"(d[3])
        : "r"(a[0]), "r"(a[1]), "r"(a[2]), "r"(a[3]), "r"(b0), "r"(b1));
}
#define CP16(dst, src) \
    asm volatile("cp.async.cg.shared.global [%0], [%1], 16;" :: "r"(dst), "l"(src))
#define CP_COMMIT() asm volatile("cp.async.commit_group;" ::: "memory")
#define CP_WAIT0()  asm volatile("cp.async.wait_group 0;" ::: "memory")

static __device__ __forceinline__ uint32_t swz(uint32_t u) {
    return u ^ ((u >> 3) & 1u);
}
static __device__ __forceinline__ float2 ldcs2(const float2* p) {
    float2 v;
    asm volatile("ld.global.cs.v2.f32 {%0,%1}, [%2];"
                 : "=f"(v.x), "=f"(v.y) : "l"(p));
    return v;
}
static __device__ __forceinline__ void stwt(float* p, float v) {
    asm volatile("st.global.wt.f32 [%0], %1;" :: "l"(p), "f"(v));
}

// ---------------------------------------------------------------------------
// aux: fused synth + prepack(2px/thread, evict-first LDG.64) + tail.
// ---------------------------------------------------------------------------
__global__ __launch_bounds__(256) void aux_kernel(
        const float* __restrict__ x,
        const int* __restrict__ task,
        const float* __restrict__ gw,
        const float* __restrict__ gb,
        const float* __restrict__ w5,
        const float* __restrict__ w3,
        const float* __restrict__ w1,
        const float* __restrict__ wa3,
        const float* __restrict__ wa5,
        float* __restrict__ out,
        int extra) {
    int bid = blockIdx.x;
    int tid = threadIdx.x;

    if (bid < SY_BLKS) {
        // ---------------- synth ----------------
        int s   = bid;
        int b   = s >> 4;
        int o   = (s & 15) * 4 + (tid >> 6);
        int i   = tid & 63;
        int t   = task[b];

        float l[NE];
        float m = -1e30f;
#pragma unroll
        for (int e = 0; e < NE; e++) {
            int eo = e * CO_ + o;
            l[e] = gw[eo * NT + t] + gb[eo];
            m = fmaxf(m, l[e]);
        }
        float ssum = 0.f;
#pragma unroll
        for (int e = 0; e < NE; e++) { l[e] = expf(l[e] - m); ssum += l[e]; }
        float inv = 1.f / ssum;
        float g0 = l[0] * inv, g1 = l[1] * inv, g2 = l[2] * inv,
              g3 = l[3] * inv, g4 = l[4] * inv;

        const float* W5 = w5 + ((size_t)o * CI_ + i) * 25;
        const float* W3 = w3 + ((size_t)o * CI_ + i) * 9;
        float c1 = g2 * w1[o * CI_ + i];
        float a3 = g3 * wa3[o * CI_ + i] * (1.f / 9.f);
        float a5 = g4 * wa5[o * CI_ + i] * (1.f / 25.f);

        int c4 = i >> 4;
        int cl = i & 15;
        __half* wb = (__half*)g_wB4;
        size_t base = (((size_t)(b * 4 + c4) * 25) * 64 + o) * 16 + cl;

#pragma unroll
        for (int ky = 0; ky < 5; ky++) {
#pragma unroll
            for (int kx = 0; kx < 5; kx++) {
                float v = g0 * W5[ky * 5 + kx] + a5;
                if (ky >= 1 && ky <= 3 && kx >= 1 && kx <= 3)
                    v += g1 * W3[(ky - 1) * 3 + (kx - 1)] + a3;
                if (ky == 2 && kx == 2) v += c1;
                wb[base + (size_t)(ky * 5 + kx) * 1024] = __float2half_rn(v);
            }
        }
    } else if (bid < SY_BLKS + PP_BLKS) {
        // ---------------- prepack: pair of pixels per thread ----------------
        int r    = bid - SY_BLKS;
        int pblk = r % PP_BLKS_PER_C;
        int c    = (r / PP_BLKS_PER_C) & 3;
        int b    = r / (PP_BLKS_PER_C * 4);
        int pr   = pblk * 256 + tid;             // pair index
        if (pr >= PP_PAIRS) return;
        int yy = pr / 66;
        int xp = (pr - yy * 66) * 2;             // even xx
        int gy = yy - 2;
        int gx = xp - 2;                          // even; pair fully in or out
        bool ok = ((unsigned)gy < (unsigned)Hh) && ((unsigned)gx < (unsigned)Ww);
        const float* src = x + (((size_t)(b * 64 + c * 16)) * Hh + gy) * Ww + gx;
        __half2 v0[8], v1[8];
#pragma unroll
        for (int j = 0; j < 8; j++) {
            float2 a = ok ? ldcs2((const float2*)(src + (size_t)(2 * j) * (Hh * Ww)))
                          : make_float2(0.f, 0.f);
            float2 bq = ok ? ldcs2((const float2*)(src + (size_t)(2 * j + 1) * (Hh * Ww)))
                           : make_float2(0.f, 0.f);
            v0[j] = __floats2half2_rn(a.x, bq.x);   // pixel xp
            v1[j] = __floats2half2_rn(a.y, bq.y);   // pixel xp+1
        }
        uint4* dst = g_xpack + ((((size_t)(b * 4 + c)) * 132 + yy) * 132 + xp) * 2;
        dst[0] = *(const uint4*)(&v0[0]);
        dst[1] = *(const uint4*)(&v0[4]);
        dst[2] = *(const uint4*)(&v1[0]);
        dst[3] = *(const uint4*)(&v1[4]);
    } else {
        // ---------------- tail ----------------
        int j = tid;
        if (j < extra && j < B_)
            out[(size_t)B_ * CO_ * Hh * Ww + j] = (float)task[j];
    }
}

// ---------------------------------------------------------------------------
// conv: persistent HMMA implicit GEMM. One sync per chunk; prefetch deferred
// past the first ky row to spread LSU pressure. Direct reg->gmem epilogue
// with write-through (no L2 pollution).
// ---------------------------------------------------------------------------
__global__ __launch_bounds__(512, 1) void conv_kernel(float* __restrict__ y) {
    extern __shared__ char smem[];
    uint32_t sbase = smem_u32(smem);

    int tid = threadIdx.x;
    int w   = tid >> 5;
    int l   = tid & 31;

    int wr = w >> 2;     // output row within CTA (0..3)
    int wx = w & 3;      // 32-px x-range

    uint32_t aU[2];
    {
        int row = l & 15;
        int kq  = (l >> 4) & 1;
#pragma unroll
        for (int s = 0; s < 2; s++) {
            int x0 = wx * 32 + s * 16;
            aU[s] = (uint32_t)(2 * (x0 + row) + kq);
        }
    }
    uint32_t bRel[4];
    {
        int ol = l & 7;
        int kh = (l >> 3) & 1;
        int g  = (l >> 4) & 1;
#pragma unroll
        for (int j = 0; j < 4; j++) {
            uint32_t u = (uint32_t)(((j * 2 + g) * 8 + ol) * 2 + kh);
            bRel[j] = swz(u) * 16;
        }
    }
    uint32_t aSw[2][5];
#pragma unroll
    for (int s = 0; s < 2; s++)
#pragma unroll
        for (int kx = 0; kx < 5; kx++) aSw[s][kx] = swz(aU[s] + 2u * kx) * 16;

    const uint32_t aOff[2] = {A0_OFF, A1_OFF};
    const uint32_t bOff[2] = {B0_OFF, B1_OFF};

    auto prefetch = [&](int tile, int c, int pb) {
        int b  = tile >> 5;
        int y0 = (tile & 31) << 2;
        const uint4* bsrc = g_wB4 + (size_t)(b * 4 + c) * 3200;
        uint32_t bdst = sbase + bOff[pb];
        for (int u = tid; u < 3200; u += 512) {
            uint32_t blk = (uint32_t)u >> 7;
            uint32_t wi  = (uint32_t)u & 127;
            CP16(bdst + ((blk << 7) + swz(wi)) * 16, (const char*)(bsrc + u));
        }
        const char* asrc = (const char*)(g_xpack +
            ((((size_t)(b * 4 + c)) * 132 + y0) * 132) * 2);
        uint32_t adst = sbase + aOff[pb];
        for (int u = tid; u < 2112; u += 512) {
            uint32_t slot = (uint32_t)u / 264;
            uint32_t wi   = (uint32_t)u - slot * 264;
            CP16(adst + slot * 4224 + swz(wi) * 16,
                 asrc + (size_t)slot * 4224 + (size_t)wi * 16);
        }
    };

    int pf_tile = blockIdx.x;
    int pf_c    = 0;
    int pf_buf  = 0;
    auto do_pf = [&]() {
        if (pf_tile < NTILES) prefetch(pf_tile, pf_c, pf_buf);
        CP_COMMIT();
        pf_buf ^= 1;
        if (++pf_c == 4) { pf_c = 0; pf_tile += NCTA; }
    };

    do_pf();   // chunk 0 of first tile in flight

    float acc[2][8][4];
    int buf = 0;

    for (int tile = blockIdx.x; tile < NTILES; tile += NCTA) {
        int b  = tile >> 5;
        int y0 = (tile & 31) << 2;

#pragma unroll
        for (int s = 0; s < 2; s++)
#pragma unroll
            for (int j = 0; j < 8; j++)
#pragma unroll
                for (int k = 0; k < 4; k++) acc[s][j][k] = 0.f;

        for (int c = 0; c < 4; c++) {
            CP_WAIT0();           // current chunk resident
            __syncthreads();      // + previous buf fully consumed by all warps

            uint32_t bufA = sbase + aOff[buf];
            uint32_t bufB = sbase + bOff[buf];

            // one k-row of compute (5 kx steps) for a given ky
            auto krow = [&](int ky) {
                uint32_t sA = bufA + (uint32_t)(wr + ky) * 4224;
#pragma unroll
                for (int kx = 0; kx < 5; kx++) {
                    uint32_t af[2][4], bf[16];
#pragma unroll
                    for (int s = 0; s < 2; s++)
                        ldsm_x4(af[s], sA + aSw[s][kx]);
                    uint32_t tb = bufB + (uint32_t)((ky * 5 + kx) * 2048);
#pragma unroll
                    for (int jn = 0; jn < 4; jn++)
                        ldsm_x4(&bf[jn * 4], tb + bRel[jn]);
#pragma unroll
                    for (int s = 0; s < 2; s++)
#pragma unroll
                        for (int g = 0; g < 4; g++) {
                            mma16816(acc[s][2 * g],     af[s], bf[g * 4],     bf[g * 4 + 1]);
                            mma16816(acc[s][2 * g + 1], af[s], bf[g * 4 + 2], bf[g * 4 + 3]);
                        }
                }
            };

            krow(0);
            do_pf();              // issue next chunk after first k-row
#pragma unroll 1
            for (int ky = 1; ky < 5; ky++) krow(ky);

            buf ^= 1;
        }

        // ---- epilogue: direct reg->gmem, write-through (sector-dense) ----
        {
            float* ybase = y + ((size_t)b * CO_ * Hh + (y0 + wr)) * Ww;
            int xq = l >> 2;
            int oq = (l & 3) << 1;
#pragma unroll
            for (int s = 0; s < 2; s++) {
                int x0 = wx * 32 + s * 16 + xq;
#pragma unroll
                for (int j = 0; j < 8; j++) {
                    int oc0 = j * 8 + oq;
                    float* p0 = ybase + (size_t)oc0 * (Hh * Ww);
                    float* p1 = ybase + (size_t)(oc0 + 1) * (Hh * Ww);
                    stwt(p0 + x0,     acc[s][j][0]);
                    stwt(p1 + x0,     acc[s][j][1]);
                    stwt(p0 + x0 + 8, acc[s][j][2]);
                    stwt(p1 + x0 + 8, acc[s][j][3]);
                }
            }
        }
    }
}

// ---------------------------------------------------------------------------
extern "C" void kernel_launch(void* const* d_in, const int* in_sizes, int n_in,
                              void* d_out, int out_size) {
    const float* x    = (const float*)d_in[0];
    const int*   task = (const int*)d_in[1];
    const float* gw   = (const float*)d_in[2];
    const float* gb   = (const float*)d_in[3];
    const float* w5   = (const float*)d_in[4];
    const float* w3   = (const float*)d_in[5];
    const float* w1   = (const float*)d_in[6];
    const float* wa3  = (const float*)d_in[7];
    const float* wa5  = (const float*)d_in[8];
    float* out = (float*)d_out;

    cudaFuncSetAttribute(conv_kernel, cudaFuncAttributeMaxDynamicSharedMemorySize,
                         SMEM_TOTAL);

    int ymain = B_ * CO_ * Hh * Ww;
    int extra = out_size - ymain;

    aux_kernel<<<AUX_BLKS, 256>>>(x, task, gw, gb, w5, w3, w1, wa3, wa5,
                                  out, extra > 0 ? extra : 0);
    conv_kernel<<<NCTA, 512, SMEM_TOTAL>>>(out);
}

// round 17
// speedup vs baseline: 1.0075x; 1.0075x over previous
#include <cuda_runtime.h>
#include <cuda_fp16.h>
#include <cstdint>

#define B_  32
#define CI_ 64
#define CO_ 64
#define Hh  128
#define Ww  128
#define NE  5
#define NT  10
#define NTILES 1024
#define NCTA   148

// ---- conv smem layout (bytes) ----
#define A0_OFF     0          // 8 slots * 132 px * 32B = 33792
#define A1_OFF     33792
#define B0_OFF     67584      // 25 taps * 64 o * 32B = 51200
#define B1_OFF     118784
#define SMEM_TOTAL 169984

// aux kernel block partitioning: synth first, then prepack (2px/thread), tail
#define SY_BLKS        (B_ * (CO_ / 4))           // 512
#define PP_PAIRS       (132 * 66)                 // 8712 pairs per (b,c)
#define PP_BLKS_PER_C  35                         // ceil(8712/256)
#define PP_BLKS        (PP_BLKS_PER_C * 4 * B_)   // 4480
#define AUX_BLKS       (SY_BLKS + PP_BLKS + 1)    // 4993

// B prepack: [b][chunk4][ky5][kx5][o64][ci16] fp16
__device__ uint4 g_wB4[409600];
// A prepack: [b][chunk4][yy132][xx132][ci16] fp16 (halo baked in as zeros)
__device__ uint4 g_xpack[4460544];

// ---------------------------------------------------------------------------
static __device__ __forceinline__ uint32_t smem_u32(const void* p) {
    uint32_t a;
    asm("{ .reg .u64 t; cvta.to.shared.u64 t, %1; cvt.u32.u64 %0, t; }"
        : "=r"(a) : "l"(p));
    return a;
}
static __device__ __forceinline__ void ldsm_x4(uint32_t* a, uint32_t addr) {
    asm volatile("ldmatrix.sync.aligned.m8n8.x4.shared.b16 {%0,%1,%2,%3}, [%4];"
                 : "=r"(a[0]), "=r"(a[1]), "=r"(a[2]), "=r"(a[3]) : "r"(addr));
}
static __device__ __forceinline__ void mma16816(float* d, const uint32_t* a,
                                                uint32_t b0, uint32_t b1) {
    asm volatile(
        "mma.sync.aligned.m16n8k16.row.col.f32.f16.f16.f32 "
        "{%0,%1,%2,%3}, {%4,%5,%6,%7}, {%8,%9}, {%0,%1,%2,%3};"
        : "+f"(d[0]), "+f"(d[1]), "+f"(d[2]), "+f"(d[3])
        : "r"(a[0]), "r"(a[1]), "r"(a[2]), "r"(a[3]), "r"(b0), "r"(b1));
}
#define CP16(dst, src) \
    asm volatile("cp.async.cg.shared.global [%0], [%1], 16;" :: "r"(dst), "l"(src))
#define CP_COMMIT() asm volatile("cp.async.commit_group;" ::: "memory")
#define CP_WAIT0()  asm volatile("cp.async.wait_group 0;" ::: "memory")

static __device__ __forceinline__ uint32_t swz(uint32_t u) {
    return u ^ ((u >> 3) & 1u);
}
static __device__ __forceinline__ void stwt(float* p, float v) {
    asm volatile("st.global.wt.f32 [%0], %1;" :: "l"(p), "f"(v));
}

// ---------------------------------------------------------------------------
// aux: fused synth + prepack(2px/thread, plain LDG.64) + tail. (R15 version)
// ---------------------------------------------------------------------------
__global__ __launch_bounds__(256) void aux_kernel(
        const float* __restrict__ x,
        const int* __restrict__ task,
        const float* __restrict__ gw,
        const float* __restrict__ gb,
        const float* __restrict__ w5,
        const float* __restrict__ w3,
        const float* __restrict__ w1,
        const float* __restrict__ wa3,
        const float* __restrict__ wa5,
        float* __restrict__ out,
        int extra) {
    int bid = blockIdx.x;
    int tid = threadIdx.x;

    if (bid < SY_BLKS) {
        // ---------------- synth ----------------
        int s   = bid;
        int b   = s >> 4;
        int o   = (s & 15) * 4 + (tid >> 6);
        int i   = tid & 63;
        int t   = task[b];

        float l[NE];
        float m = -1e30f;
#pragma unroll
        for (int e = 0; e < NE; e++) {
            int eo = e * CO_ + o;
            l[e] = gw[eo * NT + t] + gb[eo];
            m = fmaxf(m, l[e]);
        }
        float ssum = 0.f;
#pragma unroll
        for (int e = 0; e < NE; e++) { l[e] = expf(l[e] - m); ssum += l[e]; }
        float inv = 1.f / ssum;
        float g0 = l[0] * inv, g1 = l[1] * inv, g2 = l[2] * inv,
              g3 = l[3] * inv, g4 = l[4] * inv;

        const float* W5 = w5 + ((size_t)o * CI_ + i) * 25;
        const float* W3 = w3 + ((size_t)o * CI_ + i) * 9;
        float c1 = g2 * w1[o * CI_ + i];
        float a3 = g3 * wa3[o * CI_ + i] * (1.f / 9.f);
        float a5 = g4 * wa5[o * CI_ + i] * (1.f / 25.f);

        int c4 = i >> 4;
        int cl = i & 15;
        __half* wb = (__half*)g_wB4;
        size_t base = (((size_t)(b * 4 + c4) * 25) * 64 + o) * 16 + cl;

#pragma unroll
        for (int ky = 0; ky < 5; ky++) {
#pragma unroll
            for (int kx = 0; kx < 5; kx++) {
                float v = g0 * W5[ky * 5 + kx] + a5;
                if (ky >= 1 && ky <= 3 && kx >= 1 && kx <= 3)
                    v += g1 * W3[(ky - 1) * 3 + (kx - 1)] + a3;
                if (ky == 2 && kx == 2) v += c1;
                wb[base + (size_t)(ky * 5 + kx) * 1024] = __float2half_rn(v);
            }
        }
    } else if (bid < SY_BLKS + PP_BLKS) {
        // ---------------- prepack: pair of pixels per thread ----------------
        int r    = bid - SY_BLKS;
        int pblk = r % PP_BLKS_PER_C;
        int c    = (r / PP_BLKS_PER_C) & 3;
        int b    = r / (PP_BLKS_PER_C * 4);
        int pr   = pblk * 256 + tid;             // pair index
        if (pr >= PP_PAIRS) return;
        int yy = pr / 66;
        int xp = (pr - yy * 66) * 2;             // even xx
        int gy = yy - 2;
        int gx = xp - 2;                          // even; pair fully in or out
        bool ok = ((unsigned)gy < (unsigned)Hh) && ((unsigned)gx < (unsigned)Ww);
        const float* src = x + (((size_t)(b * 64 + c * 16)) * Hh + gy) * Ww + gx;
        __half2 v0[8], v1[8];
#pragma unroll
        for (int j = 0; j < 8; j++) {
            float2 a = ok ? *(const float2*)(src + (size_t)(2 * j) * (Hh * Ww))
                          : make_float2(0.f, 0.f);
            float2 bq = ok ? *(const float2*)(src + (size_t)(2 * j + 1) * (Hh * Ww))
                           : make_float2(0.f, 0.f);
            v0[j] = __floats2half2_rn(a.x, bq.x);   // pixel xp
            v1[j] = __floats2half2_rn(a.y, bq.y);   // pixel xp+1
        }
        uint4* dst = g_xpack + ((((size_t)(b * 4 + c)) * 132 + yy) * 132 + xp) * 2;
        dst[0] = *(const uint4*)(&v0[0]);
        dst[1] = *(const uint4*)(&v0[4]);
        dst[2] = *(const uint4*)(&v1[0]);
        dst[3] = *(const uint4*)(&v1[4]);
    } else {
        // ---------------- tail ----------------
        int j = tid;
        if (j < extra && j < B_)
            out[(size_t)B_ * CO_ * Hh * Ww + j] = (float)task[j];
    }
}

// ---------------------------------------------------------------------------
// conv: persistent HMMA implicit GEMM (R16 version, proven 228.6us).
// One sync per chunk; prefetch deferred past first ky row; direct
// reg->gmem write-through epilogue.
// ---------------------------------------------------------------------------
__global__ __launch_bounds__(512, 1) void conv_kernel(float* __restrict__ y) {
    extern __shared__ char smem[];
    uint32_t sbase = smem_u32(smem);

    int tid = threadIdx.x;
    int w   = tid >> 5;
    int l   = tid & 31;

    int wr = w >> 2;     // output row within CTA (0..3)
    int wx = w & 3;      // 32-px x-range

    uint32_t aU[2];
    {
        int row = l & 15;
        int kq  = (l >> 4) & 1;
#pragma unroll
        for (int s = 0; s < 2; s++) {
            int x0 = wx * 32 + s * 16;
            aU[s] = (uint32_t)(2 * (x0 + row) + kq);
        }
    }
    uint32_t bRel[4];
    {
        int ol = l & 7;
        int kh = (l >> 3) & 1;
        int g  = (l >> 4) & 1;
#pragma unroll
        for (int j = 0; j < 4; j++) {
            uint32_t u = (uint32_t)(((j * 2 + g) * 8 + ol) * 2 + kh);
            bRel[j] = swz(u) * 16;
        }
    }
    uint32_t aSw[2][5];
#pragma unroll
    for (int s = 0; s < 2; s++)
#pragma unroll
        for (int kx = 0; kx < 5; kx++) aSw[s][kx] = swz(aU[s] + 2u * kx) * 16;

    const uint32_t aOff[2] = {A0_OFF, A1_OFF};
    const uint32_t bOff[2] = {B0_OFF, B1_OFF};

    auto prefetch = [&](int tile, int c, int pb) {
        int b  = tile >> 5;
        int y0 = (tile & 31) << 2;
        const uint4* bsrc = g_wB4 + (size_t)(b * 4 + c) * 3200;
        uint32_t bdst = sbase + bOff[pb];
        for (int u = tid; u < 3200; u += 512) {
            uint32_t blk = (uint32_t)u >> 7;
            uint32_t wi  = (uint32_t)u & 127;
            CP16(bdst + ((blk << 7) + swz(wi)) * 16, (const char*)(bsrc + u));
        }
        const char* asrc = (const char*)(g_xpack +
            ((((size_t)(b * 4 + c)) * 132 + y0) * 132) * 2);
        uint32_t adst = sbase + aOff[pb];
        for (int u = tid; u < 2112; u += 512) {
            uint32_t slot = (uint32_t)u / 264;
            uint32_t wi   = (uint32_t)u - slot * 264;
            CP16(adst + slot * 4224 + swz(wi) * 16,
                 asrc + (size_t)slot * 4224 + (size_t)wi * 16);
        }
    };

    int pf_tile = blockIdx.x;
    int pf_c    = 0;
    int pf_buf  = 0;
    auto do_pf = [&]() {
        if (pf_tile < NTILES) prefetch(pf_tile, pf_c, pf_buf);
        CP_COMMIT();
        pf_buf ^= 1;
        if (++pf_c == 4) { pf_c = 0; pf_tile += NCTA; }
    };

    do_pf();   // chunk 0 of first tile in flight

    float acc[2][8][4];
    int buf = 0;

    for (int tile = blockIdx.x; tile < NTILES; tile += NCTA) {
        int b  = tile >> 5;
        int y0 = (tile & 31) << 2;

#pragma unroll
        for (int s = 0; s < 2; s++)
#pragma unroll
            for (int j = 0; j < 8; j++)
#pragma unroll
                for (int k = 0; k < 4; k++) acc[s][j][k] = 0.f;

        for (int c = 0; c < 4; c++) {
            CP_WAIT0();           // current chunk resident
            __syncthreads();      // + previous buf fully consumed by all warps

            uint32_t bufA = sbase + aOff[buf];
            uint32_t bufB = sbase + bOff[buf];

            // one k-row of compute (5 kx steps) for a given ky
            auto krow = [&](int ky) {
                uint32_t sA = bufA + (uint32_t)(wr + ky) * 4224;
#pragma unroll
                for (int kx = 0; kx < 5; kx++) {
                    uint32_t af[2][4], bf[16];
#pragma unroll
                    for (int s = 0; s < 2; s++)
                        ldsm_x4(af[s], sA + aSw[s][kx]);
                    uint32_t tb = bufB + (uint32_t)((ky * 5 + kx) * 2048);
#pragma unroll
                    for (int jn = 0; jn < 4; jn++)
                        ldsm_x4(&bf[jn * 4], tb + bRel[jn]);
#pragma unroll
                    for (int s = 0; s < 2; s++)
#pragma unroll
                        for (int g = 0; g < 4; g++) {
                            mma16816(acc[s][2 * g],     af[s], bf[g * 4],     bf[g * 4 + 1]);
                            mma16816(acc[s][2 * g + 1], af[s], bf[g * 4 + 2], bf[g * 4 + 3]);
                        }
                }
            };

            krow(0);
            do_pf();              // issue next chunk after first k-row
#pragma unroll 1
            for (int ky = 1; ky < 5; ky++) krow(ky);

            buf ^= 1;
        }

        // ---- epilogue: direct reg->gmem, write-through (sector-dense) ----
        {
            float* ybase = y + ((size_t)b * CO_ * Hh + (y0 + wr)) * Ww;
            int xq = l >> 2;
            int oq = (l & 3) << 1;
#pragma unroll
            for (int s = 0; s < 2; s++) {
                int x0 = wx * 32 + s * 16 + xq;
#pragma unroll
                for (int j = 0; j < 8; j++) {
                    int oc0 = j * 8 + oq;
                    float* p0 = ybase + (size_t)oc0 * (Hh * Ww);
                    float* p1 = ybase + (size_t)(oc0 + 1) * (Hh * Ww);
                    stwt(p0 + x0,     acc[s][j][0]);
                    stwt(p1 + x0,     acc[s][j][1]);
                    stwt(p0 + x0 + 8, acc[s][j][2]);
                    stwt(p1 + x0 + 8, acc[s][j][3]);
                }
            }
        }
    }
}

// ---------------------------------------------------------------------------
extern "C" void kernel_launch(void* const* d_in, const int* in_sizes, int n_in,
                              void* d_out, int out_size) {
    const float* x    = (const float*)d_in[0];
    const int*   task = (const int*)d_in[1];
    const float* gw   = (const float*)d_in[2];
    const float* gb   = (const float*)d_in[3];
    const float* w5   = (const float*)d_in[4];
    const float* w3   = (const float*)d_in[5];
    const float* w1   = (const float*)d_in[6];
    const float* wa3  = (const float*)d_in[7];
    const float* wa5  = (const float*)d_in[8];
    float* out = (float*)d_out;

    cudaFuncSetAttribute(conv_kernel, cudaFuncAttributeMaxDynamicSharedMemorySize,
                         SMEM_TOTAL);

    int ymain = B_ * CO_ * Hh * Ww;
    int extra = out_size - ymain;

    aux_kernel<<<AUX_BLKS, 256>>>(x, task, gw, gb, w5, w3, w1, wa3, wa5,
                                  out, extra > 0 ? extra : 0);
    conv_kernel<<<NCTA, 512, SMEM_TOTAL>>>(out);
}